// round 1
// baseline (speedup 1.0000x reference)
#include <cuda_runtime.h>

#define NF 32
#define LL 8
#define HDIM 256
#define KBINS 8
#define PP 25
#define NP 800          // NF * PP
#define MT 64           // batch rows per CTA
#define NTHREADS 256
#define HSTR 260        // smem row stride for h/r buffers
#define XSTR 33         // smem row stride for x tile

#define RMINF (-10.0f)
#define RMAXF (10.0f)
#define MINBIN (1e-4f)
#define MINSLOPE (1e-4f)

__device__ __forceinline__ float reluf(float v) { return fmaxf(v, 0.0f); }

// ---------------------------------------------------------------------------
// h = mx @ W_in + b_in   (only the 16 masked input columns are nonzero)
// 8x8 register tile per thread; writes raw (no relu) into hs (stride HSTR).
// ---------------------------------------------------------------------------
__device__ __forceinline__ void mmIn(const float* __restrict__ Wi,
                                     const float* __restrict__ bi,
                                     const float* __restrict__ xs,
                                     float* __restrict__ hs,
                                     int tid, int koff)
{
    const int tn = (tid & 31) << 3;
    const int tm = (tid >> 5) << 3;
    float acc[8][8];
#pragma unroll
    for (int c = 0; c < 8; c++) {
        float b = bi[tn + c];
#pragma unroll
        for (int r = 0; r < 8; r++) acc[r][c] = b;
    }
#pragma unroll
    for (int k = 0; k < 16; k++) {
        const int n = 2 * k + koff;
        const float* wrow = Wi + n * HDIM + tn;
        float4 w0 = *reinterpret_cast<const float4*>(wrow);
        float4 w1 = *reinterpret_cast<const float4*>(wrow + 4);
        float a[8];
#pragma unroll
        for (int r = 0; r < 8; r++) a[r] = xs[(tm + r) * XSTR + n];
#pragma unroll
        for (int r = 0; r < 8; r++) {
            acc[r][0] = fmaf(a[r], w0.x, acc[r][0]);
            acc[r][1] = fmaf(a[r], w0.y, acc[r][1]);
            acc[r][2] = fmaf(a[r], w0.z, acc[r][2]);
            acc[r][3] = fmaf(a[r], w0.w, acc[r][3]);
            acc[r][4] = fmaf(a[r], w1.x, acc[r][4]);
            acc[r][5] = fmaf(a[r], w1.y, acc[r][5]);
            acc[r][6] = fmaf(a[r], w1.z, acc[r][6]);
            acc[r][7] = fmaf(a[r], w1.w, acc[r][7]);
        }
    }
#pragma unroll
    for (int r = 0; r < 8; r++) {
        float* dp = hs + (tm + r) * HSTR + tn;
        *reinterpret_cast<float4*>(dp)     = make_float4(acc[r][0], acc[r][1], acc[r][2], acc[r][3]);
        *reinterpret_cast<float4*>(dp + 4) = make_float4(acc[r][4], acc[r][5], acc[r][6], acc[r][7]);
    }
}

// ---------------------------------------------------------------------------
// D = op( A @ W + bias )   A,D in smem stride HSTR, W global (k-major, ld=256)
// MODE 0: D = acc;  MODE 1: D = relu(acc);  MODE 2: D += relu(acc)
// ---------------------------------------------------------------------------
template <int MODE>
__device__ __forceinline__ void mm256(const float* __restrict__ W,
                                      const float* __restrict__ bias,
                                      const float* __restrict__ A,
                                      float* __restrict__ D, int tid)
{
    const int tn = (tid & 31) << 3;
    const int tm = (tid >> 5) << 3;
    float acc[8][8];
#pragma unroll
    for (int c = 0; c < 8; c++) {
        float b = bias[tn + c];
#pragma unroll
        for (int r = 0; r < 8; r++) acc[r][c] = b;
    }
#pragma unroll 4
    for (int k = 0; k < HDIM; k++) {
        const float* wrow = W + k * HDIM + tn;
        float4 w0 = *reinterpret_cast<const float4*>(wrow);
        float4 w1 = *reinterpret_cast<const float4*>(wrow + 4);
        float a[8];
#pragma unroll
        for (int r = 0; r < 8; r++) a[r] = A[(tm + r) * HSTR + k];
#pragma unroll
        for (int r = 0; r < 8; r++) {
            acc[r][0] = fmaf(a[r], w0.x, acc[r][0]);
            acc[r][1] = fmaf(a[r], w0.y, acc[r][1]);
            acc[r][2] = fmaf(a[r], w0.z, acc[r][2]);
            acc[r][3] = fmaf(a[r], w0.w, acc[r][3]);
            acc[r][4] = fmaf(a[r], w1.x, acc[r][4]);
            acc[r][5] = fmaf(a[r], w1.y, acc[r][5]);
            acc[r][6] = fmaf(a[r], w1.z, acc[r][6]);
            acc[r][7] = fmaf(a[r], w1.w, acc[r][7]);
        }
    }
#pragma unroll
    for (int r = 0; r < 8; r++) {
        float* dp = D + (tm + r) * HSTR + tn;
        if (MODE == 0) {
            *reinterpret_cast<float4*>(dp)     = make_float4(acc[r][0], acc[r][1], acc[r][2], acc[r][3]);
            *reinterpret_cast<float4*>(dp + 4) = make_float4(acc[r][4], acc[r][5], acc[r][6], acc[r][7]);
        } else if (MODE == 1) {
            *reinterpret_cast<float4*>(dp)     = make_float4(reluf(acc[r][0]), reluf(acc[r][1]), reluf(acc[r][2]), reluf(acc[r][3]));
            *reinterpret_cast<float4*>(dp + 4) = make_float4(reluf(acc[r][4]), reluf(acc[r][5]), reluf(acc[r][6]), reluf(acc[r][7]));
        } else {
            float4 o0 = *reinterpret_cast<float4*>(dp);
            float4 o1 = *reinterpret_cast<float4*>(dp + 4);
            o0.x += reluf(acc[r][0]); o0.y += reluf(acc[r][1]);
            o0.z += reluf(acc[r][2]); o0.w += reluf(acc[r][3]);
            o1.x += reluf(acc[r][4]); o1.y += reluf(acc[r][5]);
            o1.z += reluf(acc[r][6]); o1.w += reluf(acc[r][7]);
            *reinterpret_cast<float4*>(dp)     = o0;
            *reinterpret_cast<float4*>(dp + 4) = o1;
        }
    }
}

// ---------------------------------------------------------------------------
// Rational-quadratic spline for one element; p[0..7]=uw, p[8..15]=uh, p[16..24]=ud.
// Returns (y_or_x, ld_or_0). Fully unrolled so all arrays stay in registers.
// ---------------------------------------------------------------------------
__device__ __forceinline__ float2 rqs_eval(const float* __restrict__ p, float xv, float splOff)
{
    float w[KBINS], hh[KBINS], d[KBINS + 1];
    float mw = p[0], mh = p[8];
#pragma unroll
    for (int j = 1; j < KBINS; j++) { mw = fmaxf(mw, p[j]); mh = fmaxf(mh, p[8 + j]); }
    float sw = 0.f, sh = 0.f;
#pragma unroll
    for (int j = 0; j < KBINS; j++) {
        w[j]  = expf(p[j] - mw);       sw += w[j];
        hh[j] = expf(p[8 + j] - mh);   sh += hh[j];
    }
    const float span = (RMAXF - RMINF) - KBINS * MINBIN;   // 19.9992
    const float sclw = span / sw;
    const float sclh = span / sh;
#pragma unroll
    for (int j = 0; j < KBINS + 1; j++) {
        float v = p[16 + j] + splOff;
        d[j] = ((v > 15.f) ? v : log1pf(expf(v))) + MINSLOPE;
    }
    float xp[KBINS + 1], yp[KBINS + 1];
    xp[0] = RMINF; yp[0] = RMINF;
#pragma unroll
    for (int j = 0; j < KBINS; j++) {
        xp[j + 1] = xp[j] + fmaf(w[j], sclw, MINBIN);
        yp[j + 1] = yp[j] + fmaf(hh[j], sclh, MINBIN);
    }
    float xc = fminf(fmaxf(xv, RMINF), RMAXF);
    int idx = 0;
#pragma unroll
    for (int j = 1; j <= KBINS; j++) idx += (xc >= xp[j]) ? 1 : 0;
    idx = min(idx, KBINS - 1);
    float xk = xp[0], xk1 = xp[1], yk = yp[0], yk1 = yp[1], dk = d[0], dk1 = d[1];
#pragma unroll
    for (int j = 0; j < KBINS; j++) {
        if (idx == j) { xk = xp[j]; xk1 = xp[j + 1]; yk = yp[j]; yk1 = yp[j + 1]; dk = d[j]; dk1 = d[j + 1]; }
    }
    float bw = xk1 - xk;
    float bh = yk1 - yk;
    float s = bh / bw;
    float z = fminf(fmaxf((xc - xk) / bw, 0.f), 1.f);
    float omz = 1.f - z;
    float zz = z * omz;
    float denom = fmaf(dk1 + dk - 2.f * s, zz, s);
    float y = yk + bh * fmaf(s * z, z, dk * zz) / denom;
    float num = fmaf(dk1 * z, z, fmaf(2.f * s, zz, dk * omz * omz));
    float ld = 2.f * logf(s) + logf(num) - 2.f * logf(denom);
    bool inside = (xv > RMINF) && (xv < RMAXF);
    return make_float2(inside ? y : xv, inside ? ld : 0.f);
}

// ---------------------------------------------------------------------------
extern "C" __global__ void __launch_bounds__(NTHREADS, 1)
rqs_flow_kernel(const float* __restrict__ x,
                const float* __restrict__ sc_scale,
                const float* __restrict__ sc_shift,
                const float* __restrict__ W_in,  const float* __restrict__ b_in,
                const float* __restrict__ W1a,   const float* __restrict__ b1a,
                const float* __restrict__ W1b,   const float* __restrict__ b1b,
                const float* __restrict__ W2a,   const float* __restrict__ b2a,
                const float* __restrict__ W2b,   const float* __restrict__ b2b,
                const float* __restrict__ W_out, const float* __restrict__ b_out,
                const int* __restrict__ perms,
                float* __restrict__ out)
{
    extern __shared__ float smem[];
    float* hs    = smem;                    // MT*HSTR
    float* rs    = hs + MT * HSTR;          // MT*HSTR (aliased as W_out staging)
    float* xs    = rs + MT * HSTR;          // MT*XSTR
    float* lds_s = xs + MT * XSTR;          // MT

    const int tid = threadIdx.x;
    const long long base = (long long)blockIdx.x * MT;

    for (int idx = tid; idx < MT * NF; idx += NTHREADS) {
        int m = idx >> 5, n = idx & 31;
        xs[m * XSTR + n] = x[(base + m) * NF + n];
    }
    if (tid < MT) lds_s[tid] = 0.f;
    const float splOff = logf(expm1f(1.0f - MINSLOPE));
    __syncthreads();

    for (int i = 0; i < LL; i++) {
        const int koff = (i & 1) ? 0 : 1;   // conditioner-input (kept) parity
        const int toff = 1 - koff;          // transformed parity

        // ---- permute + affine (snapshot in registers) ----
        {
            const int*   pm  = perms    + i * NF;
            const float* scs = sc_scale + i * NF;
            const float* sch = sc_shift + i * NF;
            const int m  = tid >> 2;
            const int nb = (tid & 3) << 3;
            float tmp[8];
#pragma unroll
            for (int q = 0; q < 8; q++) {
                int nn = nb + q;
                tmp[q] = fmaf(xs[m * XSTR + pm[nn]], scs[nn], sch[nn]);
            }
            __syncthreads();
#pragma unroll
            for (int q = 0; q < 8; q++) xs[m * XSTR + nb + q] = tmp[q];
            __syncthreads();
        }

        // ---- conditioner MLP ----
        mmIn(W_in + i * NF * HDIM, b_in + i * HDIM, xs, hs, tid, koff);
        __syncthreads();
        mm256<1>(W1a + i * HDIM * HDIM, b1a + i * HDIM, hs, rs, tid);
        __syncthreads();
        mm256<2>(W1b + i * HDIM * HDIM, b1b + i * HDIM, rs, hs, tid);
        __syncthreads();
        mm256<1>(W2a + i * HDIM * HDIM, b2a + i * HDIM, hs, rs, tid);
        __syncthreads();
        mm256<2>(W2b + i * HDIM * HDIM, b2b + i * HDIM, rs, hs, tid);

        // ---- W_out (only 16 transformed dims) + spline ----
        {
            float* ws = rs;                                  // staging buffer
            const float* Wo = W_out + (long long)i * HDIM * NP;
            const float* bo = b_out + i * NP;
            const int nj = tid & 15;         // transformed-dim index 0..15
            const int mg = tid >> 4;         // row group 0..15
            const int n  = 2 * nj + toff;
            const int cb = n * PP;
            const int m0 = mg * 4;

            float acc[4][PP];
#pragma unroll
            for (int p = 0; p < PP; p++) {
                float b = bo[cb + p];
                acc[0][p] = b; acc[1][p] = b; acc[2][p] = b; acc[3][p] = b;
            }
            for (int kb = 0; kb < 16; kb++) {
                __syncthreads();             // prior consumers of ws/rs done
                const float4* src = reinterpret_cast<const float4*>(Wo + kb * 16 * NP);
                float4* dst = reinterpret_cast<float4*>(ws);
                for (int idx = tid; idx < (16 * NP) / 4; idx += NTHREADS) dst[idx] = src[idx];
                __syncthreads();
#pragma unroll 2
                for (int kk = 0; kk < 16; kk++) {
                    const int k = (kb << 4) + kk;
                    float h0 = fmaxf(hs[(m0 + 0) * HSTR + k], 0.f);
                    float h1 = fmaxf(hs[(m0 + 1) * HSTR + k], 0.f);
                    float h2 = fmaxf(hs[(m0 + 2) * HSTR + k], 0.f);
                    float h3 = fmaxf(hs[(m0 + 3) * HSTR + k], 0.f);
                    const float* wr = ws + kk * NP + cb;
#pragma unroll
                    for (int p = 0; p < PP; p++) {
                        float w = wr[p];
                        acc[0][p] = fmaf(h0, w, acc[0][p]);
                        acc[1][p] = fmaf(h1, w, acc[1][p]);
                        acc[2][p] = fmaf(h2, w, acc[2][p]);
                        acc[3][p] = fmaf(h3, w, acc[3][p]);
                    }
                }
            }
            float ldv[4];
#pragma unroll
            for (int mi = 0; mi < 4; mi++) {
                float xv = xs[(m0 + mi) * XSTR + n];
                float2 r = rqs_eval(acc[mi], xv, splOff);
                xs[(m0 + mi) * XSTR + n] = r.x;
                ldv[mi] = r.y;
            }
            // reduce logdet over the 16 lanes sharing this row group
#pragma unroll
            for (int off = 8; off >= 1; off >>= 1) {
#pragma unroll
                for (int mi = 0; mi < 4; mi++)
                    ldv[mi] += __shfl_xor_sync(0xffffffffu, ldv[mi], off);
            }
            if (nj == 0) {
#pragma unroll
                for (int mi = 0; mi < 4; mi++) lds_s[m0 + mi] += ldv[mi];
            }
        }
        __syncthreads();
    }

    // ---- final log-prob ----
    if (tid < MT) {
        const int m = tid;
        float s2 = 0.f;
#pragma unroll
        for (int nn = 0; nn < NF; nn++) {
            float v = xs[m * XSTR + nn];
            s2 = fmaf(v, v, s2);
        }
        float C = 0.f;
        for (int i = 0; i < LL; i++)
            for (int nn = 0; nn < NF; nn++)
                C += logf(fabsf(sc_scale[i * NF + nn]));
        out[base + m] = -0.5f * s2 - 0.5f * (float)NF * 1.8378770664093453f + lds_s[m] + C;
    }
}

// ---------------------------------------------------------------------------
extern "C" void kernel_launch(void* const* d_in, const int* in_sizes, int n_in,
                              void* d_out, int out_size)
{
    const float* x        = (const float*)d_in[0];
    const float* sc_scale = (const float*)d_in[1];
    const float* sc_shift = (const float*)d_in[2];
    const float* W_in     = (const float*)d_in[3];
    const float* b_in     = (const float*)d_in[4];
    const float* W1a      = (const float*)d_in[5];
    const float* b1a      = (const float*)d_in[6];
    const float* W1b      = (const float*)d_in[7];
    const float* b1b      = (const float*)d_in[8];
    const float* W2a      = (const float*)d_in[9];
    const float* b2a      = (const float*)d_in[10];
    const float* W2b      = (const float*)d_in[11];
    const float* b2b      = (const float*)d_in[12];
    const float* W_out    = (const float*)d_in[13];
    const float* b_out    = (const float*)d_in[14];
    const int*   perms    = (const int*)d_in[15];

    const int B = in_sizes[0] / NF;
    const int grid = B / MT;
    const size_t smem = (size_t)(2 * MT * HSTR + MT * XSTR + MT) * sizeof(float);

    cudaFuncSetAttribute(rqs_flow_kernel,
                         cudaFuncAttributeMaxDynamicSharedMemorySize, (int)smem);

    rqs_flow_kernel<<<grid, NTHREADS, smem>>>(
        x, sc_scale, sc_shift, W_in, b_in, W1a, b1a, W1b, b1b,
        W2a, b2a, W2b, b2b, W_out, b_out, perms, (float*)d_out);
}

// round 3
// speedup vs baseline: 1.5778x; 1.5778x over previous
#include <cuda_runtime.h>
#include <cstdint>

#define NF 32
#define LL 8
#define HDIM 256
#define KBINS 8
#define PP 25
#define NP 800          // NF * PP
#define MT 64           // batch rows per CTA
#define NTHREADS 512
#define HSTR 260        // smem row stride for h/r buffers (bank-spread for W_out h reads)
#define XSTR 33         // smem row stride for x tile

#define RMINF (-10.0f)
#define RMAXF (10.0f)
#define MINBIN (1e-4f)
#define MINSLOPE (1e-4f)

__device__ __forceinline__ float reluf(float v) { return fmaxf(v, 0.0f); }

__device__ __forceinline__ void cpasync16(unsigned int dst, const float* src) {
    asm volatile("cp.async.cg.shared.global [%0], [%1], 16;" :: "r"(dst), "l"(src));
}
__device__ __forceinline__ void cpcommit() {
    asm volatile("cp.async.commit_group;");
}
template <int N>
__device__ __forceinline__ void cpwait() {
    asm volatile("cp.async.wait_group %0;" :: "n"(N));
}

// ---------------------------------------------------------------------------
// h = mx @ W_in + b_in (only 16 masked input columns nonzero). 4x8 tile/thread.
// ---------------------------------------------------------------------------
__device__ __forceinline__ void mmIn(const float* __restrict__ Wi,
                                     const float* __restrict__ bi,
                                     const float* __restrict__ xs,
                                     float* __restrict__ hs,
                                     int tid, int koff)
{
    const int tn = (tid & 31) << 3;
    const int tm = (tid >> 5) << 2;
    float acc[4][8];
#pragma unroll
    for (int c = 0; c < 8; c++) {
        float b = bi[tn + c];
#pragma unroll
        for (int r = 0; r < 4; r++) acc[r][c] = b;
    }
#pragma unroll
    for (int k = 0; k < 16; k++) {
        const int n = 2 * k + koff;
        const float* wrow = Wi + n * HDIM + tn;
        float4 w0 = *reinterpret_cast<const float4*>(wrow);
        float4 w1 = *reinterpret_cast<const float4*>(wrow + 4);
        float a[4];
#pragma unroll
        for (int r = 0; r < 4; r++) a[r] = xs[(tm + r) * XSTR + n];
#pragma unroll
        for (int r = 0; r < 4; r++) {
            acc[r][0] = fmaf(a[r], w0.x, acc[r][0]);
            acc[r][1] = fmaf(a[r], w0.y, acc[r][1]);
            acc[r][2] = fmaf(a[r], w0.z, acc[r][2]);
            acc[r][3] = fmaf(a[r], w0.w, acc[r][3]);
            acc[r][4] = fmaf(a[r], w1.x, acc[r][4]);
            acc[r][5] = fmaf(a[r], w1.y, acc[r][5]);
            acc[r][6] = fmaf(a[r], w1.z, acc[r][6]);
            acc[r][7] = fmaf(a[r], w1.w, acc[r][7]);
        }
    }
#pragma unroll
    for (int r = 0; r < 4; r++) {
        float* dp = hs + (tm + r) * HSTR + tn;
        *reinterpret_cast<float4*>(dp)     = make_float4(acc[r][0], acc[r][1], acc[r][2], acc[r][3]);
        *reinterpret_cast<float4*>(dp + 4) = make_float4(acc[r][4], acc[r][5], acc[r][6], acc[r][7]);
    }
}

// ---------------------------------------------------------------------------
// D = op( A @ W + bias ), 256x256 W staged in SMEM via double-buffered cp.async.
// MODE 0: D=acc; 1: D=relu(acc); 2: D+=relu(acc)
// One __syncthreads per 16-k tile: [wait, sync, prefetch-next, compute]
// ---------------------------------------------------------------------------
template <int MODE>
__device__ __forceinline__ void mm256(const float* __restrict__ W,
                                      const float* __restrict__ bias,
                                      const float* __restrict__ A,
                                      float* __restrict__ D,
                                      const float* __restrict__ wbuf, unsigned int wsm,
                                      int tid)
{
    const int tn = (tid & 31) << 3;
    const int tm = (tid >> 5) << 2;
    float acc[4][8];
#pragma unroll
    for (int c = 0; c < 8; c++) {
        float b = bias[tn + c];
#pragma unroll
        for (int r = 0; r < 4; r++) acc[r][c] = b;
    }
    // prefetch tile 0 (rows 0..15 = 4096 floats, 1024 x 16B)
#pragma unroll
    for (int t = 0; t < 2; t++) {
        int idx = tid + t * NTHREADS;
        cpasync16(wsm + idx * 16, W + idx * 4);
    }
    cpcommit();

#pragma unroll 1
    for (int kb = 0; kb < 16; kb++) {
        cpwait<0>();
        __syncthreads();
        if (kb < 15) {
            const float* src = W + (kb + 1) * 16 * HDIM;
            unsigned int dst = wsm + (unsigned int)(((kb + 1) & 1) * 16384);
#pragma unroll
            for (int t = 0; t < 2; t++) {
                int idx = tid + t * NTHREADS;
                cpasync16(dst + idx * 16, src + idx * 4);
            }
            cpcommit();
        }
        const float* wb = wbuf + (kb & 1) * 4096;
        const float* Ab = A + tm * HSTR + kb * 16;
#pragma unroll
        for (int k4 = 0; k4 < 4; k4++) {
            float a4[4][4];
#pragma unroll
            for (int r = 0; r < 4; r++)
                *reinterpret_cast<float4*>(a4[r]) =
                    *reinterpret_cast<const float4*>(Ab + r * HSTR + k4 * 4);
#pragma unroll
            for (int kk = 0; kk < 4; kk++) {
                const float* wr = wb + (k4 * 4 + kk) * HDIM + tn;
                float4 w0 = *reinterpret_cast<const float4*>(wr);
                float4 w1 = *reinterpret_cast<const float4*>(wr + 4);
#pragma unroll
                for (int r = 0; r < 4; r++) {
                    float a = a4[r][kk];
                    acc[r][0] = fmaf(a, w0.x, acc[r][0]);
                    acc[r][1] = fmaf(a, w0.y, acc[r][1]);
                    acc[r][2] = fmaf(a, w0.z, acc[r][2]);
                    acc[r][3] = fmaf(a, w0.w, acc[r][3]);
                    acc[r][4] = fmaf(a, w1.x, acc[r][4]);
                    acc[r][5] = fmaf(a, w1.y, acc[r][5]);
                    acc[r][6] = fmaf(a, w1.z, acc[r][6]);
                    acc[r][7] = fmaf(a, w1.w, acc[r][7]);
                }
            }
        }
    }
#pragma unroll
    for (int r = 0; r < 4; r++) {
        float* dp = D + (tm + r) * HSTR + tn;
        if (MODE == 0) {
            *reinterpret_cast<float4*>(dp)     = make_float4(acc[r][0], acc[r][1], acc[r][2], acc[r][3]);
            *reinterpret_cast<float4*>(dp + 4) = make_float4(acc[r][4], acc[r][5], acc[r][6], acc[r][7]);
        } else if (MODE == 1) {
            *reinterpret_cast<float4*>(dp)     = make_float4(reluf(acc[r][0]), reluf(acc[r][1]), reluf(acc[r][2]), reluf(acc[r][3]));
            *reinterpret_cast<float4*>(dp + 4) = make_float4(reluf(acc[r][4]), reluf(acc[r][5]), reluf(acc[r][6]), reluf(acc[r][7]));
        } else {
            float4 o0 = *reinterpret_cast<float4*>(dp);
            float4 o1 = *reinterpret_cast<float4*>(dp + 4);
            o0.x += reluf(acc[r][0]); o0.y += reluf(acc[r][1]);
            o0.z += reluf(acc[r][2]); o0.w += reluf(acc[r][3]);
            o1.x += reluf(acc[r][4]); o1.y += reluf(acc[r][5]);
            o1.z += reluf(acc[r][6]); o1.w += reluf(acc[r][7]);
            *reinterpret_cast<float4*>(dp)     = o0;
            *reinterpret_cast<float4*>(dp + 4) = o1;
        }
    }
}

// ---------------------------------------------------------------------------
// Rational-quadratic spline (fully unrolled, register-resident).
// ---------------------------------------------------------------------------
__device__ __forceinline__ float2 rqs_eval(const float* __restrict__ p, float xv, float splOff)
{
    float w[KBINS], hh[KBINS], d[KBINS + 1];
    float mw = p[0], mh = p[8];
#pragma unroll
    for (int j = 1; j < KBINS; j++) { mw = fmaxf(mw, p[j]); mh = fmaxf(mh, p[8 + j]); }
    float sw = 0.f, sh = 0.f;
#pragma unroll
    for (int j = 0; j < KBINS; j++) {
        w[j]  = expf(p[j] - mw);       sw += w[j];
        hh[j] = expf(p[8 + j] - mh);   sh += hh[j];
    }
    const float span = (RMAXF - RMINF) - KBINS * MINBIN;
    const float sclw = span / sw;
    const float sclh = span / sh;
#pragma unroll
    for (int j = 0; j < KBINS + 1; j++) {
        float v = p[16 + j] + splOff;
        d[j] = ((v > 15.f) ? v : log1pf(expf(v))) + MINSLOPE;
    }
    float xp[KBINS + 1], yp[KBINS + 1];
    xp[0] = RMINF; yp[0] = RMINF;
#pragma unroll
    for (int j = 0; j < KBINS; j++) {
        xp[j + 1] = xp[j] + fmaf(w[j], sclw, MINBIN);
        yp[j + 1] = yp[j] + fmaf(hh[j], sclh, MINBIN);
    }
    float xc = fminf(fmaxf(xv, RMINF), RMAXF);
    int idx = 0;
#pragma unroll
    for (int j = 1; j <= KBINS; j++) idx += (xc >= xp[j]) ? 1 : 0;
    idx = min(idx, KBINS - 1);
    float xk = xp[0], xk1 = xp[1], yk = yp[0], yk1 = yp[1], dk = d[0], dk1 = d[1];
#pragma unroll
    for (int j = 1; j < KBINS; j++) {
        if (idx == j) { xk = xp[j]; xk1 = xp[j + 1]; yk = yp[j]; yk1 = yp[j + 1]; dk = d[j]; dk1 = d[j + 1]; }
    }
    float bw = xk1 - xk;
    float bh = yk1 - yk;
    float s = bh / bw;
    float z = fminf(fmaxf((xc - xk) / bw, 0.f), 1.f);
    float omz = 1.f - z;
    float zz = z * omz;
    float denom = fmaf(dk1 + dk - 2.f * s, zz, s);
    float y = yk + bh * fmaf(s * z, z, dk * zz) / denom;
    float num = fmaf(dk1 * z, z, fmaf(2.f * s, zz, dk * omz * omz));
    float ld = 2.f * logf(s) + logf(num) - 2.f * logf(denom);
    bool inside = (xv > RMINF) && (xv < RMAXF);
    return make_float2(inside ? y : xv, inside ? ld : 0.f);
}

// ---------------------------------------------------------------------------
extern "C" __global__ void __launch_bounds__(NTHREADS, 1)
rqs_flow_kernel(const float* __restrict__ x,
                const float* __restrict__ sc_scale,
                const float* __restrict__ sc_shift,
                const float* __restrict__ W_in,  const float* __restrict__ b_in,
                const float* __restrict__ W1a,   const float* __restrict__ b1a,
                const float* __restrict__ W1b,   const float* __restrict__ b1b,
                const float* __restrict__ W2a,   const float* __restrict__ b2a,
                const float* __restrict__ W2b,   const float* __restrict__ b2b,
                const float* __restrict__ W_out, const float* __restrict__ b_out,
                const int* __restrict__ perms,
                float* __restrict__ out)
{
    extern __shared__ float smem[];
    float* hs    = smem;                    // MT*HSTR
    float* rs    = hs + MT * HSTR;          // MT*HSTR (reused as W_out staging, 2x 8x800)
    float* wbuf  = rs + MT * HSTR;          // 2 * 16*256 = 8192
    float* xs    = wbuf + 8192;             // MT*XSTR
    float* lds_s = xs + MT * XSTR;          // MT

    const int tid = threadIdx.x;
    const long long base = (long long)blockIdx.x * MT;
    const unsigned int wsm  = (unsigned int)__cvta_generic_to_shared(wbuf);
    const unsigned int rssm = (unsigned int)__cvta_generic_to_shared(rs);

    for (int idx = tid; idx < MT * NF; idx += NTHREADS) {
        int m = idx >> 5, n = idx & 31;
        xs[m * XSTR + n] = x[(base + m) * NF + n];
    }
    if (tid < MT) lds_s[tid] = 0.f;
    const float splOff = logf(expm1f(1.0f - MINSLOPE));
    __syncthreads();

    for (int i = 0; i < LL; i++) {
        const int koff = (i & 1) ? 0 : 1;   // conditioner-input parity
        const int toff = 1 - koff;          // transformed parity

        // ---- permute + affine ----
        {
            const int*   pm  = perms    + i * NF;
            const float* scs = sc_scale + i * NF;
            const float* sch = sc_shift + i * NF;
            const int m  = tid >> 3;
            const int nb = (tid & 7) << 2;
            float tmp[4];
#pragma unroll
            for (int q = 0; q < 4; q++) {
                int nn = nb + q;
                tmp[q] = fmaf(xs[m * XSTR + pm[nn]], scs[nn], sch[nn]);
            }
            __syncthreads();
#pragma unroll
            for (int q = 0; q < 4; q++) xs[m * XSTR + nb + q] = tmp[q];
            __syncthreads();
        }

        // ---- conditioner MLP ----
        mmIn(W_in + i * NF * HDIM, b_in + i * HDIM, xs, hs, tid, koff);
        mm256<1>(W1a + i * HDIM * HDIM, b1a + i * HDIM, hs, rs, wbuf, wsm, tid);
        mm256<2>(W1b + i * HDIM * HDIM, b1b + i * HDIM, rs, hs, wbuf, wsm, tid);
        mm256<1>(W2a + i * HDIM * HDIM, b2a + i * HDIM, hs, rs, wbuf, wsm, tid);
        mm256<2>(W2b + i * HDIM * HDIM, b2b + i * HDIM, rs, hs, wbuf, wsm, tid);
        __syncthreads();   // all reads of rs done before W_out staging overwrites it

        // ---- W_out (only 16 transformed dims) + spline ----
        {
            const float* Wo = W_out + (long long)i * HDIM * NP;
            const float* bo = b_out + i * NP;
            const int nj = tid & 15;         // transformed-dim index 0..15
            const int mg = tid >> 4;         // row group 0..31
            const int n  = 2 * nj + toff;
            const int cb = n * PP;
            const int m0 = mg * 2;

            float acc[2][PP];
#pragma unroll
            for (int p = 0; p < PP; p++) {
                float b = bo[cb + p];
                acc[0][p] = b; acc[1][p] = b;
            }
            // prefetch block 0 (rows 0..7, 6400 floats = 1600 x 16B)
            for (int t = tid; t < 1600; t += NTHREADS)
                cpasync16(rssm + t * 16, Wo + t * 4);
            cpcommit();

#pragma unroll 1
            for (int kb = 0; kb < 32; kb++) {
                cpwait<0>();
                __syncthreads();
                if (kb < 31) {
                    const float* src = Wo + (kb + 1) * 8 * NP;
                    unsigned int dst = rssm + (unsigned int)(((kb + 1) & 1) * (8 * NP * 4));
                    for (int t = tid; t < 1600; t += NTHREADS)
                        cpasync16(dst + t * 16, src + t * 4);
                    cpcommit();
                }
                const float* ws = rs + (kb & 1) * (8 * NP);
#pragma unroll 2
                for (int kk = 0; kk < 8; kk++) {
                    const int k = (kb << 3) + kk;
                    float h0 = fmaxf(hs[(m0 + 0) * HSTR + k], 0.f);
                    float h1 = fmaxf(hs[(m0 + 1) * HSTR + k], 0.f);
                    const float* wr = ws + kk * NP + cb;
#pragma unroll
                    for (int p = 0; p < PP; p++) {
                        float w = wr[p];
                        acc[0][p] = fmaf(h0, w, acc[0][p]);
                        acc[1][p] = fmaf(h1, w, acc[1][p]);
                    }
                }
            }
            float ldv[2];
#pragma unroll
            for (int mi = 0; mi < 2; mi++) {
                float xv = xs[(m0 + mi) * XSTR + n];
                float2 r = rqs_eval(acc[mi], xv, splOff);
                xs[(m0 + mi) * XSTR + n] = r.x;
                ldv[mi] = r.y;
            }
            // reduce over the 16 lanes (nj) sharing each row group
#pragma unroll
            for (int off = 8; off >= 1; off >>= 1) {
#pragma unroll
                for (int mi = 0; mi < 2; mi++)
                    ldv[mi] += __shfl_xor_sync(0xffffffffu, ldv[mi], off);
            }
            if (nj == 0) {
#pragma unroll
                for (int mi = 0; mi < 2; mi++) lds_s[m0 + mi] += ldv[mi];
            }
        }
        __syncthreads();
    }

    // ---- final log-prob ----
    if (tid < MT) {
        const int m = tid;
        float s2 = 0.f;
#pragma unroll
        for (int nn = 0; nn < NF; nn++) {
            float v = xs[m * XSTR + nn];
            s2 = fmaf(v, v, s2);
        }
        float C = 0.f;
        for (int i = 0; i < LL; i++)
            for (int nn = 0; nn < NF; nn++)
                C += logf(fabsf(sc_scale[i * NF + nn]));
        out[base + m] = -0.5f * s2 - 0.5f * (float)NF * 1.8378770664093453f + lds_s[m] + C;
    }
}

// ---------------------------------------------------------------------------
extern "C" void kernel_launch(void* const* d_in, const int* in_sizes, int n_in,
                              void* d_out, int out_size)
{
    const float* x        = (const float*)d_in[0];
    const float* sc_scale = (const float*)d_in[1];
    const float* sc_shift = (const float*)d_in[2];
    const float* W_in     = (const float*)d_in[3];
    const float* b_in     = (const float*)d_in[4];
    const float* W1a      = (const float*)d_in[5];
    const float* b1a      = (const float*)d_in[6];
    const float* W1b      = (const float*)d_in[7];
    const float* b1b      = (const float*)d_in[8];
    const float* W2a      = (const float*)d_in[9];
    const float* b2a      = (const float*)d_in[10];
    const float* W2b      = (const float*)d_in[11];
    const float* b2b      = (const float*)d_in[12];
    const float* W_out    = (const float*)d_in[13];
    const float* b_out    = (const float*)d_in[14];
    const int*   perms    = (const int*)d_in[15];

    const int B = in_sizes[0] / NF;
    const int grid = B / MT;
    const size_t smem = (size_t)(2 * MT * HSTR + 8192 + MT * XSTR + MT) * sizeof(float);

    cudaFuncSetAttribute(rqs_flow_kernel,
                         cudaFuncAttributeMaxDynamicSharedMemorySize, (int)smem);

    rqs_flow_kernel<<<grid, NTHREADS, smem>>>(
        x, sc_scale, sc_shift, W_in, b_in, W1a, b1a, W1b, b1b,
        W2a, b2a, W2b, b2b, W_out, b_out, perms, (float*)d_out);
}

// round 4
// speedup vs baseline: 2.4754x; 1.5689x over previous
#include <cuda_runtime.h>
#include <cstdint>

#define NF 32
#define LL 8
#define HDIM 256
#define KBINS 8
#define PP 25
#define NP 800
#define MT 64
#define NTHREADS 512
#define MSTR 66         // transposed activation stride: [k][m], 64 rows + 2 pad

#define RMINF (-10.0f)
#define RMAXF (10.0f)
#define MINBIN (1e-4f)
#define MINSLOPE (1e-4f)

typedef unsigned long long u64;

__device__ __forceinline__ u64 pack2(float lo, float hi) {
    u64 r; asm("mov.b64 %0, {%1,%2};" : "=l"(r) : "f"(lo), "f"(hi)); return r;
}
__device__ __forceinline__ float2 unpack2(u64 v) {
    float2 r; asm("mov.b64 {%0,%1}, %2;" : "=f"(r.x), "=f"(r.y) : "l"(v)); return r;
}
__device__ __forceinline__ void fma2(u64& d, u64 a, u64 b) {
    asm("fma.rn.f32x2 %0, %1, %2, %0;" : "+l"(d) : "l"(a), "l"(b));
}

__device__ __forceinline__ void cpasync16(unsigned int dst, const float* src) {
    asm volatile("cp.async.cg.shared.global [%0], [%1], 16;" :: "r"(dst), "l"(src));
}
__device__ __forceinline__ void cpcommit() {
    asm volatile("cp.async.commit_group;");
}
template <int N>
__device__ __forceinline__ void cpwait() {
    asm volatile("cp.async.wait_group %0;" :: "n"(N));
}

// ---------------------------------------------------------------------------
// hT[c][m] = (mx @ W_in + b_in)^T ; only 16 masked input features contribute.
// Warp w: cols [16w,16w+16); lane: rows {2l, 2l+1}. W reads broadcast from gmem.
// ---------------------------------------------------------------------------
__device__ __forceinline__ void mmIn(const float* __restrict__ Wi,
                                     const float* __restrict__ bi,
                                     const float* __restrict__ xsT,
                                     float* __restrict__ hT,
                                     int warpid, int lane, int koff)
{
    const int cb = warpid << 4;
    const int m0 = lane << 1;
    u64 acc[2][8];
    const ulonglong2* bp = reinterpret_cast<const ulonglong2*>(bi + cb);
#pragma unroll
    for (int q = 0; q < 4; q++) {
        ulonglong2 b = bp[q];
        acc[0][2*q] = b.x; acc[0][2*q+1] = b.y;
        acc[1][2*q] = b.x; acc[1][2*q+1] = b.y;
    }
#pragma unroll
    for (int k = 0; k < 16; k++) {
        const int n = 2*k + koff;
        float2 av = *reinterpret_cast<const float2*>(xsT + n*MSTR + m0);
        u64 a0 = pack2(av.x, av.x);
        u64 a1 = pack2(av.y, av.y);
        const ulonglong2* wp = reinterpret_cast<const ulonglong2*>(Wi + n*HDIM + cb);
#pragma unroll
        for (int q = 0; q < 4; q++) {
            ulonglong2 w = wp[q];
            fma2(acc[0][2*q],   a0, w.x);
            fma2(acc[0][2*q+1], a0, w.y);
            fma2(acc[1][2*q],   a1, w.x);
            fma2(acc[1][2*q+1], a1, w.y);
        }
    }
#pragma unroll
    for (int q = 0; q < 8; q++) {
        float2 r0 = unpack2(acc[0][q]);
        float2 r1 = unpack2(acc[1][q]);
        *reinterpret_cast<float2*>(hT + (cb + 2*q)*MSTR + m0)     = make_float2(r0.x, r1.x);
        *reinterpret_cast<float2*>(hT + (cb + 2*q + 1)*MSTR + m0) = make_float2(r0.y, r1.y);
    }
}

// ---------------------------------------------------------------------------
// DT = op( AT^T @ W + bias )^T with W staged via double-buffered cp.async.
// AT/DT transposed [k][m] stride MSTR. MODE 1: D=relu; MODE 2: D+=relu.
// Warp w owns 16 cols (broadcast W reads); lane owns 2 rows.
// ---------------------------------------------------------------------------
template <int MODE>
__device__ __forceinline__ void mm256(const float* __restrict__ W,
                                      const float* __restrict__ bias,
                                      const float* __restrict__ AT,
                                      float* __restrict__ DT,
                                      const float* __restrict__ wbuf, unsigned int wsm,
                                      int warpid, int lane)
{
    const int cb = warpid << 4;
    const int m0 = lane << 1;
    const int tid = (warpid << 5) + lane;
    u64 acc[2][8];
    const ulonglong2* bp = reinterpret_cast<const ulonglong2*>(bias + cb);
#pragma unroll
    for (int q = 0; q < 4; q++) {
        ulonglong2 b = bp[q];
        acc[0][2*q] = b.x; acc[0][2*q+1] = b.y;
        acc[1][2*q] = b.x; acc[1][2*q+1] = b.y;
    }
    // prefetch k-tile 0 (16 rows x 256 = 4096 floats)
#pragma unroll
    for (int t = 0; t < 2; t++) {
        int idx = tid + t * NTHREADS;
        cpasync16(wsm + idx * 16, W + idx * 4);
    }
    cpcommit();

#pragma unroll 1
    for (int kb = 0; kb < 16; kb++) {
        cpwait<0>();
        __syncthreads();
        if (kb < 15) {
            const float* src = W + (kb + 1) * 16 * HDIM;
            unsigned int dst = wsm + (unsigned int)(((kb + 1) & 1) * 16384);
#pragma unroll
            for (int t = 0; t < 2; t++) {
                int idx = tid + t * NTHREADS;
                cpasync16(dst + idx * 16, src + idx * 4);
            }
            cpcommit();
        }
        const float* wb = wbuf + (kb & 1) * 4096;
        const float* Ab = AT + kb * 16 * MSTR + m0;
#pragma unroll
        for (int kk = 0; kk < 16; kk++) {
            float2 av = *reinterpret_cast<const float2*>(Ab + kk * MSTR);
            u64 a0 = pack2(av.x, av.x);
            u64 a1 = pack2(av.y, av.y);
            const ulonglong2* wp = reinterpret_cast<const ulonglong2*>(wb + kk * HDIM + cb);
#pragma unroll
            for (int q = 0; q < 4; q++) {
                ulonglong2 w = wp[q];
                fma2(acc[0][2*q],   a0, w.x);
                fma2(acc[0][2*q+1], a0, w.y);
                fma2(acc[1][2*q],   a1, w.x);
                fma2(acc[1][2*q+1], a1, w.y);
            }
        }
    }
#pragma unroll
    for (int q = 0; q < 8; q++) {
        float2 r0 = unpack2(acc[0][q]);
        float2 r1 = unpack2(acc[1][q]);
        float2 v0 = make_float2(r0.x, r1.x);    // col cb+2q, rows m0,m0+1
        float2 v1 = make_float2(r0.y, r1.y);    // col cb+2q+1
        float* d0 = DT + (cb + 2*q) * MSTR + m0;
        float* d1 = DT + (cb + 2*q + 1) * MSTR + m0;
        if (MODE == 1) {
            *reinterpret_cast<float2*>(d0) = make_float2(fmaxf(v0.x,0.f), fmaxf(v0.y,0.f));
            *reinterpret_cast<float2*>(d1) = make_float2(fmaxf(v1.x,0.f), fmaxf(v1.y,0.f));
        } else {
            float2 o0 = *reinterpret_cast<float2*>(d0);
            float2 o1 = *reinterpret_cast<float2*>(d1);
            o0.x += fmaxf(v0.x,0.f); o0.y += fmaxf(v0.y,0.f);
            o1.x += fmaxf(v1.x,0.f); o1.y += fmaxf(v1.y,0.f);
            *reinterpret_cast<float2*>(d0) = o0;
            *reinterpret_cast<float2*>(d1) = o1;
        }
    }
}

// ---------------------------------------------------------------------------
// Rational-quadratic spline (register-resident, fast-math transcendentals).
// ---------------------------------------------------------------------------
__device__ __forceinline__ float2 rqs_eval(const float* __restrict__ p, float xv, float splOff)
{
    float w[KBINS], hh[KBINS], d[KBINS + 1];
    float mw = p[0], mh = p[8];
#pragma unroll
    for (int j = 1; j < KBINS; j++) { mw = fmaxf(mw, p[j]); mh = fmaxf(mh, p[8 + j]); }
    float sw = 0.f, sh = 0.f;
#pragma unroll
    for (int j = 0; j < KBINS; j++) {
        w[j]  = __expf(p[j] - mw);       sw += w[j];
        hh[j] = __expf(p[8 + j] - mh);   sh += hh[j];
    }
    const float span = (RMAXF - RMINF) - KBINS * MINBIN;
    const float sclw = __fdividef(span, sw);
    const float sclh = __fdividef(span, sh);
#pragma unroll
    for (int j = 0; j < KBINS + 1; j++) {
        float v = p[16 + j] + splOff;
        d[j] = ((v > 15.f) ? v : __logf(1.f + __expf(v))) + MINSLOPE;
    }
    float xp[KBINS + 1], yp[KBINS + 1];
    xp[0] = RMINF; yp[0] = RMINF;
#pragma unroll
    for (int j = 0; j < KBINS; j++) {
        xp[j + 1] = xp[j] + fmaf(w[j], sclw, MINBIN);
        yp[j + 1] = yp[j] + fmaf(hh[j], sclh, MINBIN);
    }
    float xc = fminf(fmaxf(xv, RMINF), RMAXF);
    int idx = 0;
#pragma unroll
    for (int j = 1; j <= KBINS; j++) idx += (xc >= xp[j]) ? 1 : 0;
    idx = min(idx, KBINS - 1);
    float xk = xp[0], xk1 = xp[1], yk = yp[0], yk1 = yp[1], dk = d[0], dk1 = d[1];
#pragma unroll
    for (int j = 1; j < KBINS; j++) {
        if (idx == j) { xk = xp[j]; xk1 = xp[j + 1]; yk = yp[j]; yk1 = yp[j + 1]; dk = d[j]; dk1 = d[j + 1]; }
    }
    float bw = xk1 - xk;
    float bh = yk1 - yk;
    float s = __fdividef(bh, bw);
    float z = fminf(fmaxf(__fdividef(xc - xk, bw), 0.f), 1.f);
    float omz = 1.f - z;
    float zz = z * omz;
    float denom = fmaf(dk1 + dk - 2.f * s, zz, s);
    float y = yk + bh * __fdividef(fmaf(s * z, z, dk * zz), denom);
    float num = fmaf(dk1 * z, z, fmaf(2.f * s, zz, dk * omz * omz));
    float ld = 2.f * __logf(s) + __logf(num) - 2.f * __logf(denom);
    bool inside = (xv > RMINF) && (xv < RMAXF);
    return make_float2(inside ? y : xv, inside ? ld : 0.f);
}

// ---------------------------------------------------------------------------
extern "C" __global__ void __launch_bounds__(NTHREADS, 1)
rqs_flow_kernel(const float* __restrict__ x,
                const float* __restrict__ sc_scale,
                const float* __restrict__ sc_shift,
                const float* __restrict__ W_in,  const float* __restrict__ b_in,
                const float* __restrict__ W1a,   const float* __restrict__ b1a,
                const float* __restrict__ W1b,   const float* __restrict__ b1b,
                const float* __restrict__ W2a,   const float* __restrict__ b2a,
                const float* __restrict__ W2b,   const float* __restrict__ b2b,
                const float* __restrict__ W_out, const float* __restrict__ b_out,
                const int* __restrict__ perms,
                float* __restrict__ out)
{
    extern __shared__ float smem[];
    float* hT    = smem;                    // 256*MSTR
    float* rT    = hT + HDIM * MSTR;        // 256*MSTR (reused: W_out per-warp staging)
    float* wbuf  = rT + HDIM * MSTR;        // 2 * 16*256
    float* xsT   = wbuf + 8192;             // 32*MSTR
    float* lds_s = xsT + NF * MSTR;         // 64

    const int tid    = threadIdx.x;
    const int warpid = tid >> 5;
    const int lane   = tid & 31;
    const long long base = (long long)blockIdx.x * MT;
    const unsigned int wsm = (unsigned int)__cvta_generic_to_shared(wbuf);

    // load x transposed: xsT[n][m]
    {
        const int m  = tid >> 3;
        const int n4 = (tid & 7) << 2;
        float4 gx = *reinterpret_cast<const float4*>(x + (base + m) * NF + n4);
        xsT[(n4 + 0) * MSTR + m] = gx.x;
        xsT[(n4 + 1) * MSTR + m] = gx.y;
        xsT[(n4 + 2) * MSTR + m] = gx.z;
        xsT[(n4 + 3) * MSTR + m] = gx.w;
    }
    if (tid < MT) lds_s[tid] = 0.f;
    const float splOff = logf(expm1f(1.0f - MINSLOPE));
    __syncthreads();

    for (int i = 0; i < LL; i++) {
        const int koff = (i & 1) ? 0 : 1;   // conditioner-input parity
        const int toff = 1 - koff;          // transformed parity

        // ---- permute + affine (on transposed tile) ----
        {
            const int*   pm  = perms    + i * NF;
            const float* scs = sc_scale + i * NF;
            const float* sch = sc_shift + i * NF;
            const int n  = tid >> 4;            // 0..31
            const int ms = (tid & 15) << 2;     // 0..60
            const float s  = scs[n];
            const float sh = sch[n];
            const int   pn = pm[n];
            float tmp[4];
#pragma unroll
            for (int q = 0; q < 4; q++)
                tmp[q] = fmaf(xsT[pn * MSTR + ms + q], s, sh);
            __syncthreads();
#pragma unroll
            for (int q = 0; q < 4; q++)
                xsT[n * MSTR + ms + q] = tmp[q];
            __syncthreads();
        }

        // ---- conditioner MLP (all buffers transposed [k][m]) ----
        mmIn(W_in + i * NF * HDIM, b_in + i * HDIM, xsT, hT, warpid, lane, koff);
        mm256<1>(W1a + i * HDIM * HDIM, b1a + i * HDIM, hT, rT, wbuf, wsm, warpid, lane);
        mm256<2>(W1b + i * HDIM * HDIM, b1b + i * HDIM, rT, hT, wbuf, wsm, warpid, lane);
        mm256<1>(W2a + i * HDIM * HDIM, b2a + i * HDIM, hT, rT, wbuf, wsm, warpid, lane);
        mm256<2>(W2b + i * HDIM * HDIM, b2b + i * HDIM, rT, hT, wbuf, wsm, warpid, lane);
        __syncthreads();   // all reads of rT done before W_out staging reuses it

        // ---- W_out (16 transformed dims; warp = one dim, lane = 2 rows) + spline ----
        {
            const float* Wo = W_out + (long long)i * HDIM * NP;
            const float* bo = b_out + i * NP;
            const int n   = 2 * warpid + toff;
            const int cbW = n * PP;
            const int m0  = lane << 1;
            float* wsp = rT + warpid * 224;      // private 8x28 staging slice

            u64 acc[2][14];
#pragma unroll
            for (int q = 0; q < 12; q++) {
                u64 b = pack2(bo[cbW + 2*q], bo[cbW + 2*q + 1]);
                acc[0][q] = b; acc[1][q] = b;
            }
            {
                u64 b = pack2(bo[cbW + 24], 0.f);
                acc[0][12] = b; acc[1][12] = b;
                u64 z = pack2(0.f, 0.f);
                acc[0][13] = z; acc[1][13] = z;
            }
            // prime loads for block 0
            float rw[8];
#pragma unroll
            for (int kk = 0; kk < 8; kk++)
                rw[kk] = (lane < PP) ? Wo[kk * NP + cbW + lane] : 0.f;

#pragma unroll 1
            for (int kb = 0; kb < 32; kb++) {
                __syncwarp();
#pragma unroll
                for (int kk = 0; kk < 8; kk++)
                    if (lane < 28) wsp[kk * 28 + lane] = (lane < PP) ? rw[kk] : 0.f;
                __syncwarp();
                if (kb < 31) {
#pragma unroll
                    for (int kk = 0; kk < 8; kk++)
                        rw[kk] = (lane < PP) ? Wo[((kb + 1) * 8 + kk) * NP + cbW + lane] : 0.f;
                }
#pragma unroll
                for (int kk = 0; kk < 8; kk++) {
                    const int k = kb * 8 + kk;
                    float2 hv = *reinterpret_cast<const float2*>(hT + k * MSTR + m0);
                    float h0 = fmaxf(hv.x, 0.f);
                    float h1 = fmaxf(hv.y, 0.f);
                    u64 a0 = pack2(h0, h0);
                    u64 a1 = pack2(h1, h1);
                    const ulonglong2* wp = reinterpret_cast<const ulonglong2*>(wsp + kk * 28);
#pragma unroll
                    for (int q = 0; q < 7; q++) {
                        ulonglong2 w = wp[q];
                        fma2(acc[0][2*q],   a0, w.x);
                        fma2(acc[1][2*q],   a1, w.x);
                        fma2(acc[0][2*q+1], a0, w.y);
                        fma2(acc[1][2*q+1], a1, w.y);
                    }
                }
            }
            // spline for rows m0, m0+1
            float ldv[2];
#pragma unroll
            for (int mi = 0; mi < 2; mi++) {
                float pr[28];
#pragma unroll
                for (int q = 0; q < 14; q++) {
                    float2 u = unpack2(acc[mi][q]);
                    pr[2*q] = u.x; pr[2*q + 1] = u.y;
                }
                float xv = xsT[n * MSTR + m0 + mi];
                float2 r = rqs_eval(pr, xv, splOff);
                xsT[n * MSTR + m0 + mi] = r.x;
                ldv[mi] = r.y;
            }
            atomicAdd(&lds_s[m0],     ldv[0]);
            atomicAdd(&lds_s[m0 + 1], ldv[1]);
        }
        __syncthreads();
    }

    // ---- final log-prob ----
    if (tid < MT) {
        const int m = tid;
        float s2 = 0.f;
#pragma unroll
        for (int nn = 0; nn < NF; nn++) {
            float v = xsT[nn * MSTR + m];
            s2 = fmaf(v, v, s2);
        }
        float C = 0.f;
        for (int i = 0; i < LL; i++)
            for (int nn = 0; nn < NF; nn++)
                C += logf(fabsf(sc_scale[i * NF + nn]));
        out[base + m] = -0.5f * s2 - 0.5f * (float)NF * 1.8378770664093453f + lds_s[m] + C;
    }
}

// ---------------------------------------------------------------------------
extern "C" void kernel_launch(void* const* d_in, const int* in_sizes, int n_in,
                              void* d_out, int out_size)
{
    const float* x        = (const float*)d_in[0];
    const float* sc_scale = (const float*)d_in[1];
    const float* sc_shift = (const float*)d_in[2];
    const float* W_in     = (const float*)d_in[3];
    const float* b_in     = (const float*)d_in[4];
    const float* W1a      = (const float*)d_in[5];
    const float* b1a      = (const float*)d_in[6];
    const float* W1b      = (const float*)d_in[7];
    const float* b1b      = (const float*)d_in[8];
    const float* W2a      = (const float*)d_in[9];
    const float* b2a      = (const float*)d_in[10];
    const float* W2b      = (const float*)d_in[11];
    const float* b2b      = (const float*)d_in[12];
    const float* W_out    = (const float*)d_in[13];
    const float* b_out    = (const float*)d_in[14];
    const int*   perms    = (const int*)d_in[15];

    const int B = in_sizes[0] / NF;
    const int grid = B / MT;
    // hT + rT + wbuf + xsT + lds
    const size_t smem = (size_t)(2 * HDIM * MSTR + 8192 + NF * MSTR + MT) * sizeof(float);

    cudaFuncSetAttribute(rqs_flow_kernel,
                         cudaFuncAttributeMaxDynamicSharedMemorySize, (int)smem);

    rqs_flow_kernel<<<grid, NTHREADS, smem>>>(
        x, sc_scale, sc_shift, W_in, b_in, W1a, b1a, W1b, b1b,
        W2a, b2a, W2b, b2b, W_out, b_out, perms, (float*)d_out);
}